// round 7
// baseline (speedup 1.0000x reference)
#include <cuda_runtime.h>

typedef unsigned long long ull;

#define NTOT 51840000   // 405*80*80*20

__device__ float g_mask1[6400];
__device__ float g_mask2[6400];

__global__ void mask_prep(const float* __restrict__ a1, const float* __restrict__ a2)
{
    int p = blockIdx.x * blockDim.x + threadIdx.x;
    if (p < 6400) {
        float s1 = 0.f, s2 = 0.f;
        const float* p1 = a1 + p * 20;
        const float* p2 = a2 + p * 20;
        #pragma unroll
        for (int z = 0; z < 20; ++z) { s1 += p1[z]; s2 += p2[z]; }
        g_mask1[p] = fminf(fmaxf(s1, 0.f), 1.f);
        g_mask2[p] = fminf(fmaxf(s2, 0.f), 1.f);
    }
}

__device__ __forceinline__ void unpack2(ull v, float& lo, float& hi) {
    asm("mov.b64 {%0, %1}, %2;" : "=f"(lo), "=f"(hi) : "l"(v));
}
__device__ __forceinline__ void fma2(ull& d, ull a, ull b) {
    asm("fma.rn.f32x2 %0, %1, %2, %0;" : "+l"(d) : "l"(a), "l"(b));
}
__device__ __forceinline__ ull shiftpair(ull a, ull b) {
    ull r;
    asm("{\n\t.reg .b32 alo, ahi, blo, bhi;\n\t"
        "mov.b64 {alo, ahi}, %1;\n\t"
        "mov.b64 {blo, bhi}, %2;\n\t"
        "mov.b64 %0, {ahi, blo};\n\t}"
        : "=l"(r) : "l"(a), "l"(b));
    return r;
}
__device__ __forceinline__ void cp16(unsigned dst, const void* src) {
    asm volatile("cp.async.cg.shared.global [%0], [%1], 16;" :: "r"(dst), "l"(src));
}
__device__ __forceinline__ void cp_commit() {
    asm volatile("cp.async.commit_group;" ::: "memory");
}
template<int N> __device__ __forceinline__ void cp_wait() {
    asm volatile("cp.async.wait_group %0;" :: "n"(N) : "memory");
}

// block: 240 threads, tid = zq + 5*x2c + 80*djg (zq fastest -> coalesced stores)
// grid : (x2b 6, y 80, di 9); dj = djg*3 + jl, x = x2g + 4 - dj
// 8 phases x 4 channels, TRIPLE-buffered cp.async (1 barrier per phase):
//  f1 buf: [c4][xl24][q5] quads (480 q = 7680 B each); xg = x2g0 + xl - 4, zero-pad
//  f2 buf: [c4][x2 16][13 quads] (832 q = 13312 B each); guard quads 0 & 6 zero,
//          quads 1..5 = z 0..19 unshifted
// smem = 3*7680 + 3*13312 = 62976 B -> 3 blocks/SM
#define F1B 7680
#define F2B 13312
#define F2BASE 23040
#define CADV 512000   // 4 channels * 128000 floats

__global__ void __launch_bounds__(240, 3) corr_kernel(
    const float* __restrict__ f1, const float* __restrict__ f2, float* __restrict__ out)
{
    extern __shared__ float smem[];
    const unsigned sb = (unsigned)__cvta_generic_to_shared(smem);

    const int x2b  = blockIdx.x;
    const int y    = blockIdx.y;
    const int di   = blockIdx.z;
    const int x2g0 = x2b * 16 - 4;
    const int y2   = y + di - 4;
    const bool yok = ((unsigned)y2 < 80u);
    const int tid  = threadIdx.x;

    const int zq  = tid % 5;
    const int x2c = (tid / 5) & 15;
    const int djg = tid / 80;
    const int x2g = x2g0 + x2c;

    ull acc[30];
    #pragma unroll
    for (int i = 0; i < 30; ++i) acc[i] = 0ull;

    if (yok) {
        // ---- fill assignments (src offsets in floats; <0 = skip) ----
        int f1off[2]; unsigned f1dst[2];
        #pragma unroll
        for (int k = 0; k < 2; ++k) {
            int idx = tid + 240 * k;            // 0..479 quads
            int c  = idx / 120;
            int r  = idx - c * 120;
            int xl = r / 5;
            int q  = r - xl * 5;
            int xg = x2g0 + xl - 4;
            f1dst[k] = sb + idx * 16;
            f1off[k] = ((unsigned)xg < 80u)
                       ? (c * 128000 + y * 1600 + xg * 20 + 4 * q) : (int)0x80000000;
        }
        int f2off[2]; unsigned f2dst[2];
        #pragma unroll
        for (int k = 0; k < 2; ++k) {
            int j = tid + 240 * k;              // 0..319 copies
            int i = j / 5;
            int m = j - i * 5;
            int c   = i >> 4;
            int x2l = i & 15;
            int x2  = x2g0 + x2l;
            f2dst[k] = sb + F2BASE + ((c * 16 + x2l) * 13 + 1 + m) * 16;
            f2off[k] = (j < 320 && (unsigned)x2 < 80u)
                       ? (c * 128000 + y2 * 1600 + x2 * 20 + 4 * m) : (int)0x80000000;
        }

        // ---- zero all 3 buffer pairs (guards / OOB stay zero forever) ----
        {
            float4 z4 = make_float4(0.f, 0.f, 0.f, 0.f);
            for (int i = tid; i < 3936; i += 240) ((float4*)smem)[i] = z4;
        }
        __syncthreads();

        // ---- prologue: issue phases 0 and 1 ----
        #pragma unroll
        for (int g = 0; g < 2; ++g) {
            const unsigned b1 = g * F1B, b2 = g * F2B;
            const int adv = g * CADV;
            if (f1off[0] >= 0) cp16(f1dst[0] + b1, f1 + f1off[0] + adv);
            if (f1off[1] >= 0) cp16(f1dst[1] + b1, f1 + f1off[1] + adv);
            if (f2off[0] >= 0) cp16(f2dst[0] + b2, f2 + f2off[0] + adv);
            if (f2off[1] >= 0) cp16(f2dst[1] + b2, f2 + f2off[1] + adv);
            cp_commit();
        }

        const int aq0 = (x2c + 8 - djg * 3) * 5 + zq;   // f1 quad idx (jl subtracts 5)
        const int bq0 = x2c * 13 + zq;                  // f2 quad idx within channel

        #pragma unroll
        for (int p = 0; p < 8; ++p) {
            if (p < 7) cp_wait<1>(); else cp_wait<0>();
            __syncthreads();
            // issue phase p+2 into buffer (p+2)%3 (that buffer's compute ended
            // at phase p-1; the barrier above orders it)
            if (p < 6) {
                const int g = p + 2;
                const unsigned b1 = (g % 3) * F1B, b2 = (g % 3) * F2B;
                const int adv = g * CADV;
                if (f1off[0] >= 0) cp16(f1dst[0] + b1, f1 + f1off[0] + adv);
                if (f1off[1] >= 0) cp16(f1dst[1] + b1, f1 + f1off[1] + adv);
                if (f2off[0] >= 0) cp16(f2dst[0] + b2, f2 + f2off[0] + adv);
                if (f2off[1] >= 0) cp16(f2dst[1] + b2, f2 + f2off[1] + adv);
                cp_commit();
            }
            // ---- compute phase p from buffer p%3 ----
            const float* f1b = smem + (p % 3) * (F1B / 4);
            const float* f2b = smem + (F2BASE + (p % 3) * F2B) / 4;
            #pragma unroll
            for (int cl = 0; cl < 4; ++cl) {
                const float* bp = f2b + (cl * 208 + bq0) * 4;
                ull q0hi = *(const ull*)(bp + 2);                 // z 4zq-2,4zq-1
                ulonglong2 Q1 = *(const ulonglong2*)(bp + 4);     // z 4zq..4zq+3
                ull q2lo = *(const ull*)(bp + 8);                 // z 4zq+4,4zq+5
                ull P1 = shiftpair(q0hi, Q1.x);
                ull P3 = shiftpair(Q1.x, Q1.y);
                ull P5 = shiftpair(Q1.y, q2lo);
                #pragma unroll
                for (int jl = 0; jl < 3; ++jl) {
                    ulonglong2 av = *(const ulonglong2*)(f1b + (cl * 120 + aq0 - 5 * jl) * 4);
                    ull a01 = av.x, a23 = av.y;
                    ull* A = acc + jl * 10;
                    fma2(A[0], a01, q0hi); fma2(A[1], a23, Q1.x);   // dk=0
                    fma2(A[2], a01, P1  ); fma2(A[3], a23, P3  );   // dk=1
                    fma2(A[4], a01, Q1.x); fma2(A[5], a23, Q1.y);   // dk=2
                    fma2(A[6], a01, P3  ); fma2(A[7], a23, P5  );   // dk=3
                    fma2(A[8], a01, Q1.y); fma2(A[9], a23, q2lo);   // dk=4
                }
            }
        }
    }

    // ---- epilogue: coalesced streaming stores (z-fastest across lanes) ----
    {
        const bool x2ok = ((unsigned)x2g < 80u);
        const bool spin = yok && x2ok;
        const float m2v = spin ? g_mask2[y2 * 80 + x2g] : 1.f;
        const float inv = 1.f / 32.f;
        #pragma unroll
        for (int jl = 0; jl < 3; ++jl) {
            const int dj = djg * 3 + jl;
            const int x  = x2g + 4 - dj;
            if ((unsigned)x < 80u) {
                const float m1  = g_mask1[y * 80 + x];
                const float mIn = m1 * m2v;
                float* pc = out + (size_t)(di * 9 + dj) * 128000
                                + y * 1600 + x * 20 + 4 * zq;
                float* pm = pc + NTOT;
                #pragma unroll
                for (int dk = 0; dk < 5; ++dk) {
                    float4 cv;
                    unpack2(acc[jl * 10 + dk * 2 + 0], cv.x, cv.y);
                    unpack2(acc[jl * 10 + dk * 2 + 1], cv.z, cv.w);
                    cv.x *= inv; cv.y *= inv; cv.z *= inv; cv.w *= inv;
                    __stcs((float4*)pc, cv);
                    float4 mv;
                    {
                        float* mp = (float*)&mv;
                        #pragma unroll
                        for (int zl = 0; zl < 4; ++zl) {
                            int z2 = 4 * zq + zl + dk - 2;
                            mp[zl] = (spin && (unsigned)z2 < 20u) ? mIn : m1;
                        }
                    }
                    __stcs((float4*)pm, mv);
                    pc += (size_t)81 * 128000;
                    pm += (size_t)81 * 128000;
                }
            }
        }
    }
}

extern "C" void kernel_launch(void* const* d_in, const int* in_sizes, int n_in,
                              void* d_out, int out_size)
{
    (void)in_sizes; (void)n_in; (void)out_size;
    const float* f1 = (const float*)d_in[0];
    const float* a1 = (const float*)d_in[1];
    const float* f2 = (const float*)d_in[2];
    const float* a2 = (const float*)d_in[3];
    float* out = (float*)d_out;

    cudaFuncSetAttribute(corr_kernel, cudaFuncAttributeMaxDynamicSharedMemorySize, 62976);

    mask_prep<<<25, 256>>>(a1, a2);
    corr_kernel<<<dim3(6, 80, 9), 240, 62976>>>(f1, f2, out);
}